// round 3
// baseline (speedup 1.0000x reference)
#include <cuda_runtime.h>
#include <cuda_bf16.h>

#define B 8
#define S 512
#define E 64
#define H 8
#define BH (B*H)

__device__ float g_ctx[B * S * E];

// ---- packed f32x2 helpers (sm_103a) ---------------------------------------
__device__ __forceinline__ unsigned long long pk2(float lo, float hi) {
    unsigned long long r;
    asm("mov.b64 %0, {%1, %2};" : "=l"(r) : "f"(lo), "f"(hi));
    return r;
}
__device__ __forceinline__ void upk2(unsigned long long v, float& lo, float& hi) {
    asm("mov.b64 {%0, %1}, %2;" : "=f"(lo), "=f"(hi) : "l"(v));
}
__device__ __forceinline__ unsigned long long fma2(unsigned long long a,
                                                   unsigned long long b,
                                                   unsigned long long c) {
    unsigned long long d;
    asm("fma.rn.f32x2 %0, %1, %2, %3;" : "=l"(d) : "l"(a), "l"(b), "l"(c));
    return d;
}
__device__ __forceinline__ unsigned long long mul2(unsigned long long a,
                                                   unsigned long long b) {
    unsigned long long d;
    asm("mul.rn.f32x2 %0, %1, %2;" : "=l"(d) : "l"(a), "l"(b));
    return d;
}

// ---------------------------------------------------------------------------
// Kernel 1: quantum heads (analytic cos prefix products) + attention.
// Grid (16, 64): 32-query chunk x (b,h). 256 threads: 8 threads per query,
// each covering keys j = g + 8*i. 1024 blocks -> ~7 blocks/SM, 55 warps/SM.
// ---------------------------------------------------------------------------
__global__ __launch_bounds__(256) void qattn_kernel(
    const float* __restrict__ x,      // [B, S, E]
    const float* __restrict__ theta,  // [8]
    float* __restrict__ ctx)          // [B*S, 64]
{
    __shared__ __align__(16) float Ks[S * 8];   // 16 KB

    const int bh  = blockIdx.y;
    const int b   = bh >> 3;
    const int h   = bh & 7;
    const int tid = threadIdx.x;      // 0..255

    float th[8];
#pragma unroll
    for (int j = 0; j < 8; ++j) th[j] = __ldg(theta + j);

    // Build K tile: 2 rows per thread.
#pragma unroll
    for (int rr = 0; rr < 2; ++rr) {
        const int s = tid + rr * 256;
        const float* xr = x + ((size_t)(b * S + s)) * E + h * 8;
        float4 v0 = *(const float4*)(xr);
        float4 v1 = *(const float4*)(xr + 4);
        float c0 = __cosf(v0.x + th[0]);
        float c1 = __cosf(v0.y + th[1]);
        float c2 = __cosf(v0.z + th[2]);
        float c3 = __cosf(v0.w + th[3]);
        float c4 = __cosf(v1.x + th[4]);
        float c5 = __cosf(v1.y + th[5]);
        float c6 = __cosf(v1.z + th[6]);
        float c7 = __cosf(v1.w + th[7]);
        float q1 = c0 * c1;
        float q2 = q1 * c2;
        float q3 = q2 * c3;
        float q4 = q3 * c4;
        float q5 = q4 * c5;
        float q6 = q5 * c6;
        float q7 = q6 * c7;
        float q0 = c1 * c2 * c3 * c4 * c5 * c6 * c7;
        ((float4*)Ks)[s * 2 + 0] = make_float4(q0, q1, q2, q3);
        ((float4*)Ks)[s * 2 + 1] = make_float4(q4, q5, q6, q7);
    }
    __syncthreads();

    const int q = blockIdx.x * 32 + (tid >> 3);   // query row
    const int g = tid & 7;                        // key-split lane (8-way)

    const float sc = 0.35355339059327373f * 1.4426950408889634f; // scale*log2e
    float4 qa = ((const float4*)Ks)[q * 2 + 0];
    float4 qb = ((const float4*)Ks)[q * 2 + 1];
    unsigned long long q01 = pk2(qa.x * sc, qa.y * sc);
    unsigned long long q23 = pk2(qa.z * sc, qa.w * sc);
    unsigned long long q45 = pk2(qb.x * sc, qb.y * sc);
    unsigned long long q67 = pk2(qb.z * sc, qb.w * sc);

    unsigned long long acc01 = 0ull, acc23 = 0ull, acc45 = 0ull, acc67 = 0ull;
    float l = 0.f;

    const ulonglong2* Kp = (const ulonglong2*)Ks + g * 2;  // start at row g
#pragma unroll 8
    for (int i = 0; i < 64; ++i) {            // keys g, g+8, g+16, ...
        ulonglong2 kA = Kp[i * 16 + 0];       // (k0,k1),(k2,k3)
        ulonglong2 kB = Kp[i * 16 + 1];       // (k4,k5),(k6,k7)
        unsigned long long d2 =
            fma2(q01, kA.x, fma2(q23, kA.y, fma2(q45, kB.x, mul2(q67, kB.y))));
        float dl, dh; upk2(d2, dl, dh);
        float w;
        asm("ex2.approx.f32 %0, %1;" : "=f"(w) : "f"(dl + dh));
        l += w;
        unsigned long long w2 = pk2(w, w);
        acc01 = fma2(w2, kA.x, acc01);
        acc23 = fma2(w2, kA.y, acc23);
        acc45 = fma2(w2, kB.x, acc45);
        acc67 = fma2(w2, kB.y, acc67);
    }

    // reduce across the 8 split lanes (contiguous within the warp)
    float a[9];
    upk2(acc01, a[0], a[1]);
    upk2(acc23, a[2], a[3]);
    upk2(acc45, a[4], a[5]);
    upk2(acc67, a[6], a[7]);
    a[8] = l;
#pragma unroll
    for (int v = 0; v < 9; ++v) {
        a[v] += __shfl_xor_sync(0xffffffffu, a[v], 1);
        a[v] += __shfl_xor_sync(0xffffffffu, a[v], 2);
        a[v] += __shfl_xor_sync(0xffffffffu, a[v], 4);
    }

    if (g == 0) {
        float inv = 1.f / a[8];
        float* cp = ctx + ((size_t)(b * S + q)) * E + h * 8;
        *(float4*)(cp + 0) = make_float4(a[0] * inv, a[1] * inv, a[2] * inv, a[3] * inv);
        *(float4*)(cp + 4) = make_float4(a[4] * inv, a[5] * inv, a[6] * inv, a[7] * inv);
    }
}

// ---------------------------------------------------------------------------
// Kernel 2: out = ctx @ W^T + b, gmem-direct, no syncs.
// One thread per (row, 8 outputs): 32768 threads, 128 blocks x 256.
// Warp: 4 ctx rows (broadcast loads) x 8 e-groups (8 W lines per load).
// ---------------------------------------------------------------------------
__global__ __launch_bounds__(256) void proj_kernel(
    const float* __restrict__ ctx,   // [4096, 64]
    const float* __restrict__ W,     // [64, 64]  (e, k)
    const float* __restrict__ bo,    // [64]
    float* __restrict__ out)         // [4096, 64]
{
    const int t  = blockIdx.x * 256 + threadIdx.x;   // 0..32767
    const int n  = t >> 3;                           // row 0..4095
    const int e0 = (t & 7) * 8;                      // 8 outputs per thread

    const float4* c  = (const float4*)(ctx + (size_t)n * 64);
    const float4* w0 = (const float4*)(W + (size_t)e0 * 64);

    float acc[8] = {};
#pragma unroll
    for (int k4 = 0; k4 < 16; ++k4) {
        float4 cv = __ldg(c + k4);
#pragma unroll
        for (int j = 0; j < 8; ++j) {
            float4 wv = __ldg(w0 + j * 16 + k4);
            acc[j] = fmaf(cv.x, wv.x, acc[j]);
            acc[j] = fmaf(cv.y, wv.y, acc[j]);
            acc[j] = fmaf(cv.z, wv.z, acc[j]);
            acc[j] = fmaf(cv.w, wv.w, acc[j]);
        }
    }

    float4 b0 = __ldg((const float4*)(bo + e0));
    float4 b1 = __ldg((const float4*)(bo + e0 + 4));
    float4 o0 = make_float4(acc[0] + b0.x, acc[1] + b0.y, acc[2] + b0.z, acc[3] + b0.w);
    float4 o1 = make_float4(acc[4] + b1.x, acc[5] + b1.y, acc[6] + b1.z, acc[7] + b1.w);
    *(float4*)(out + (size_t)n * 64 + e0)     = o0;
    *(float4*)(out + (size_t)n * 64 + e0 + 4) = o1;
}

extern "C" void kernel_launch(void* const* d_in, const int* in_sizes, int n_in,
                              void* d_out, int out_size)
{
    const float* x     = (const float*)d_in[0];  // [8, 512, 64]
    const float* theta = (const float*)d_in[1];  // [8]
    const float* W_o   = (const float*)d_in[2];  // [64, 64]
    const float* b_o   = (const float*)d_in[3];  // [64]
    float* out = (float*)d_out;

    float* ctx;
    cudaGetSymbolAddress((void**)&ctx, g_ctx);

    dim3 grid1(S / 32, BH);              // (16, 64) = 1024 blocks
    qattn_kernel<<<grid1, 256>>>(x, theta, ctx);

    proj_kernel<<<(B * S * E / 8) / 256, 256>>>(ctx, W_o, b_o, out);
}

// round 5
// speedup vs baseline: 1.9674x; 1.9674x over previous
#include <cuda_runtime.h>
#include <cuda_bf16.h>

#define B 8
#define S 512
#define E 64
#define H 8
#define BH (B*H)

__device__ float g_ctx[B * S * E];

// ---- packed f32x2 helpers (sm_103a) ---------------------------------------
__device__ __forceinline__ unsigned long long pk2(float lo, float hi) {
    unsigned long long r;
    asm("mov.b64 %0, {%1, %2};" : "=l"(r) : "f"(lo), "f"(hi));
    return r;
}
__device__ __forceinline__ void upk2(unsigned long long v, float& lo, float& hi) {
    asm("mov.b64 {%0, %1}, %2;" : "=f"(lo), "=f"(hi) : "l"(v));
}
__device__ __forceinline__ unsigned long long fma2(unsigned long long a,
                                                   unsigned long long b,
                                                   unsigned long long c) {
    unsigned long long d;
    asm("fma.rn.f32x2 %0, %1, %2, %3;" : "=l"(d) : "l"(a), "l"(b), "l"(c));
    return d;
}
__device__ __forceinline__ unsigned long long mul2(unsigned long long a,
                                                   unsigned long long b) {
    unsigned long long d;
    asm("mul.rn.f32x2 %0, %1, %2;" : "=l"(d) : "l"(a), "l"(b));
    return d;
}

// ---------------------------------------------------------------------------
// Kernel 1: quantum heads (analytic cos prefix products) + attention.
// EXACT R2 configuration (measured ~18.4us): block = (b,h) x 128-query chunk,
// 512 threads, 4 threads per query on interleaved keys (conflict-free LDS).
// ---------------------------------------------------------------------------
__global__ __launch_bounds__(512) void qattn_kernel(
    const float* __restrict__ x,      // [B, S, E]
    const float* __restrict__ theta,  // [8]
    float* __restrict__ ctx)          // [B*S, 64]
{
    __shared__ __align__(16) float Ks[S * 8];   // 16 KB

    const int bh  = blockIdx.y;
    const int b   = bh >> 3;
    const int h   = bh & 7;
    const int tid = threadIdx.x;      // 0..511

    float th[8];
#pragma unroll
    for (int j = 0; j < 8; ++j) th[j] = __ldg(theta + j);

    // Build K: one row per thread.
    {
        const float* xr = x + ((size_t)(b * S + tid)) * E + h * 8;
        float4 v0 = *(const float4*)(xr);
        float4 v1 = *(const float4*)(xr + 4);
        float c0 = __cosf(v0.x + th[0]);
        float c1 = __cosf(v0.y + th[1]);
        float c2 = __cosf(v0.z + th[2]);
        float c3 = __cosf(v0.w + th[3]);
        float c4 = __cosf(v1.x + th[4]);
        float c5 = __cosf(v1.y + th[5]);
        float c6 = __cosf(v1.z + th[6]);
        float c7 = __cosf(v1.w + th[7]);
        float q1 = c0 * c1;
        float q2 = q1 * c2;
        float q3 = q2 * c3;
        float q4 = q3 * c4;
        float q5 = q4 * c5;
        float q6 = q5 * c6;
        float q7 = q6 * c7;
        float q0 = c1 * c2 * c3 * c4 * c5 * c6 * c7;
        ((float4*)Ks)[tid * 2 + 0] = make_float4(q0, q1, q2, q3);
        ((float4*)Ks)[tid * 2 + 1] = make_float4(q4, q5, q6, q7);
    }
    __syncthreads();

    const int q = blockIdx.x * 128 + (tid >> 2);  // query row
    const int g = tid & 3;                        // key-split lane

    const float sc = 0.35355339059327373f * 1.4426950408889634f; // scale*log2e
    float4 qa = ((const float4*)Ks)[q * 2 + 0];
    float4 qb = ((const float4*)Ks)[q * 2 + 1];
    unsigned long long q01 = pk2(qa.x * sc, qa.y * sc);
    unsigned long long q23 = pk2(qa.z * sc, qa.w * sc);
    unsigned long long q45 = pk2(qb.x * sc, qb.y * sc);
    unsigned long long q67 = pk2(qb.z * sc, qb.w * sc);

    unsigned long long acc01 = 0ull, acc23 = 0ull, acc45 = 0ull, acc67 = 0ull;
    float l = 0.f;

    const ulonglong2* Kp = (const ulonglong2*)Ks + g * 2;  // row g
#pragma unroll 4
    for (int i = 0; i < 128; ++i) {           // keys g, g+4, g+8, ...
        ulonglong2 kA = Kp[i * 8 + 0];        // (k0,k1),(k2,k3)
        ulonglong2 kB = Kp[i * 8 + 1];        // (k4,k5),(k6,k7)
        unsigned long long d2 =
            fma2(q01, kA.x, fma2(q23, kA.y, fma2(q45, kB.x, mul2(q67, kB.y))));
        float dl, dh; upk2(d2, dl, dh);
        float w;
        asm("ex2.approx.f32 %0, %1;" : "=f"(w) : "f"(dl + dh));
        l += w;
        unsigned long long w2 = pk2(w, w);
        acc01 = fma2(w2, kA.x, acc01);
        acc23 = fma2(w2, kA.y, acc23);
        acc45 = fma2(w2, kB.x, acc45);
        acc67 = fma2(w2, kB.y, acc67);
    }

    // reduce across the 4 split lanes (consecutive lanes within warp)
    float a[9];
    upk2(acc01, a[0], a[1]);
    upk2(acc23, a[2], a[3]);
    upk2(acc45, a[4], a[5]);
    upk2(acc67, a[6], a[7]);
    a[8] = l;
#pragma unroll
    for (int v = 0; v < 9; ++v) {
        a[v] += __shfl_xor_sync(0xffffffffu, a[v], 1);
        a[v] += __shfl_xor_sync(0xffffffffu, a[v], 2);
    }

    if (g == 0) {
        float inv = 1.f / a[8];
        float* cp = ctx + ((size_t)(b * S + q)) * E + h * 8;
        *(float4*)(cp + 0) = make_float4(a[0] * inv, a[1] * inv, a[2] * inv, a[3] * inv);
        *(float4*)(cp + 4) = make_float4(a[4] * inv, a[5] * inv, a[6] * inv, a[7] * inv);
    }
}

// ---------------------------------------------------------------------------
// Kernel 2: out = ctx @ W^T + b.
// 256 blocks x 128 threads, 16 rows/block. W transposed in smem (Wt[k][e],
// pad 68: 16B-aligned rows, e contiguous -> warp's 16 LDS.128 = 256B, no
// conflicts). Thread tile = 2 rows x 4 cols; 6 LDS.128 per 32 FMA.
// ---------------------------------------------------------------------------
__global__ __launch_bounds__(128) void proj_kernel(
    const float* __restrict__ ctx,   // [4096, 64]
    const float* __restrict__ W,     // [64, 64]  (e, k)
    const float* __restrict__ bo,    // [64]
    float* __restrict__ out)         // [4096, 64]
{
    __shared__ __align__(16) float Wt[64][68];   // Wt[k][e]
    __shared__ __align__(16) float Cs[16][68];
    __shared__ float bs[64];

    const int tid  = threadIdx.x;     // 0..127
    const int row0 = blockIdx.x * 16;

    // load + transpose W (one-time; 4-way store conflicts are fine)
    for (int i = tid; i < 64 * 64; i += 128) {
        int e = i >> 6, k = i & 63;
        Wt[k][e] = W[i];
    }
    // load ctx tile (float4, coalesced, aligned stores: 68 % 4 == 0)
    for (int i = tid * 4; i < 16 * 64; i += 128 * 4) {
        float4 c = *(const float4*)(ctx + (size_t)row0 * 64 + i);
        *(float4*)&Cs[i >> 6][i & 63] = c;
    }
    if (tid < 64) bs[tid] = bo[tid];
    __syncthreads();

    const int rg = tid >> 4;          // 0..7 -> rows r0, r0+1
    const int et = tid & 15;          // e0 = et*4
    const int r0 = rg * 2;
    const int e0 = et * 4;

    float4 acc0 = make_float4(0.f, 0.f, 0.f, 0.f);
    float4 acc1 = make_float4(0.f, 0.f, 0.f, 0.f);

#pragma unroll
    for (int k4 = 0; k4 < 16; ++k4) {
        const int k0 = k4 * 4;
        float4 ca = *(const float4*)&Cs[r0 + 0][k0];   // broadcast (16 lanes)
        float4 cb = *(const float4*)&Cs[r0 + 1][k0];
#pragma unroll
        for (int j = 0; j < 4; ++j) {
            float4 w = *(const float4*)&Wt[k0 + j][e0]; // 16 lanes x 16B, conflict-free
            float cj0 = (j == 0) ? ca.x : (j == 1) ? ca.y : (j == 2) ? ca.z : ca.w;
            float cj1 = (j == 0) ? cb.x : (j == 1) ? cb.y : (j == 2) ? cb.z : cb.w;
            acc0.x = fmaf(cj0, w.x, acc0.x);
            acc0.y = fmaf(cj0, w.y, acc0.y);
            acc0.z = fmaf(cj0, w.z, acc0.z);
            acc0.w = fmaf(cj0, w.w, acc0.w);
            acc1.x = fmaf(cj1, w.x, acc1.x);
            acc1.y = fmaf(cj1, w.y, acc1.y);
            acc1.z = fmaf(cj1, w.z, acc1.z);
            acc1.w = fmaf(cj1, w.w, acc1.w);
        }
    }

    float4 bb = *(const float4*)&bs[e0];
    acc0.x += bb.x; acc0.y += bb.y; acc0.z += bb.z; acc0.w += bb.w;
    acc1.x += bb.x; acc1.y += bb.y; acc1.z += bb.z; acc1.w += bb.w;
    *(float4*)(out + (size_t)(row0 + r0 + 0) * 64 + e0) = acc0;
    *(float4*)(out + (size_t)(row0 + r0 + 1) * 64 + e0) = acc1;
}

extern "C" void kernel_launch(void* const* d_in, const int* in_sizes, int n_in,
                              void* d_out, int out_size)
{
    const float* x     = (const float*)d_in[0];  // [8, 512, 64]
    const float* theta = (const float*)d_in[1];  // [8]
    const float* W_o   = (const float*)d_in[2];  // [64, 64]
    const float* b_o   = (const float*)d_in[3];  // [64]
    float* out = (float*)d_out;

    float* ctx;
    cudaGetSymbolAddress((void**)&ctx, g_ctx);

    dim3 grid1(S / 128, BH);             // (4, 64) = 256 blocks x 512 thr
    qattn_kernel<<<grid1, 512>>>(x, theta, ctx);

    proj_kernel<<<256, 128>>>(ctx, W_o, b_o, out);
}